// round 14
// baseline (speedup 1.0000x reference)
#include <cuda_runtime.h>
#include <math.h>

#define BB 512
#define TT 1024
#define EE 64
#define HH 32
#define PP 720

#define CH 16                       // steps per ring chunk
#define NRING 4                     // ring depth (chunks)
#define ENC_CHUNKS (TT / CH)        // 64
#define TRA_CHUNKS (PP / CH)        // 45

typedef unsigned long long u64;

// ---------------- scratch (device globals: no allocation allowed) ----------
__device__ float g_z0[(size_t)TT * BB * HH];   // [t][b][h]
__device__ float g_ts1[(size_t)PP * BB * HH];  // [p][b][h]

#define WBAR() asm volatile("" ::: "memory")

// ---------------- packed fp32x2 helpers (Blackwell FFMA2) ------------------
__device__ __forceinline__ u64 pk(float a, float b) {
    u64 r; asm("mov.b64 %0, {%1,%2};" : "=l"(r) : "f"(a), "f"(b)); return r;
}
__device__ __forceinline__ float2 upk(u64 v) {
    float2 r; asm("mov.b64 {%0,%1}, %2;" : "=f"(r.x), "=f"(r.y) : "l"(v)); return r;
}
__device__ __forceinline__ u64 fma2(u64 a, u64 b, u64 c) {
    u64 d; asm("fma.rn.f32x2 %0, %1, %2, %3;" : "=l"(d) : "l"(a), "l"(b), "l"(c)); return d;
}
__device__ __forceinline__ u64 add2(u64 a, u64 b) {
    u64 d; asm("add.rn.f32x2 %0, %1, %2;" : "=l"(d) : "l"(a), "l"(b)); return d;
}

// fast tanh: tanh(x) = 1 - 2/(1+exp(2x)); exact at both saturations.
__device__ __forceinline__ float ftanh(float x) {
    float e;
    asm("ex2.approx.f32 %0, %1;" : "=f"(e) : "f"(x * 2.885390081777927f));
    return 1.0f - __fdividef(2.0f, e + 1.0f);
}

// exact-GELU via Abramowitz-Stegun 7.1.26 erf (abs err <= 1.5e-7).
__device__ __forceinline__ float gelu(float x) {
    const float u = x * 0.70710678118654752f;
    const float au = fabsf(u);
    const float t = __fdividef(1.0f, fmaf(0.3275911f, au, 1.0f));
    const float e = __expf(-u * u);
    float p = fmaf(t, 1.061405429f, -1.453152027f);
    p = fmaf(t, p, 1.421413741f);
    p = fmaf(t, p, -0.284496736f);
    p = fmaf(t, p, 0.254829592f);
    const float erf_abs = fmaf(-p * t, e, 1.0f);
    const float er = copysignf(erf_abs, u);
    return 0.5f * x * (1.0f + er);
}

// dot(32-float shared vector, packed weight row) + init; 4 split chains
__device__ __forceinline__ float dot32w(const u64* wp,
                                        const float* __restrict__ sh,
                                        float init) {
    const u64 ZZ = pk(0.0f, 0.0f);
    u64 a = pk(init, 0.0f), b = ZZ, c = ZZ, d = ZZ;
#pragma unroll
    for (int q = 0; q < 4; q++) {
        ulonglong2 v0 = *(const ulonglong2*)&sh[8 * q];
        ulonglong2 v1 = *(const ulonglong2*)&sh[8 * q + 4];
        a = fma2(v0.x, wp[4 * q + 0], a);
        b = fma2(v0.y, wp[4 * q + 1], b);
        c = fma2(v1.x, wp[4 * q + 2], c);
        d = fma2(v1.y, wp[4 * q + 3], d);
    }
    float2 r = upk(add2(add2(a, b), add2(c, d)));
    return r.x + r.y;
}

// TWO dots over the SAME shared vector (single LDS round), 4 chains each.
__device__ __forceinline__ void dual_dot(const u64* wa, const u64* wb,
                                         const float* __restrict__ sh,
                                         float ia, float ib,
                                         float& oa, float& ob) {
    const u64 ZZ = pk(0.0f, 0.0f);
    u64 a0 = pk(ia, 0.0f), a1 = ZZ, a2 = ZZ, a3 = ZZ;
    u64 b0 = pk(ib, 0.0f), b1 = ZZ, b2 = ZZ, b3 = ZZ;
#pragma unroll
    for (int q = 0; q < 4; q++) {
        ulonglong2 v0 = *(const ulonglong2*)&sh[8 * q];
        ulonglong2 v1 = *(const ulonglong2*)&sh[8 * q + 4];
        a0 = fma2(v0.x, wa[4 * q + 0], a0);
        a1 = fma2(v0.y, wa[4 * q + 1], a1);
        a2 = fma2(v1.x, wa[4 * q + 2], a2);
        a3 = fma2(v1.y, wa[4 * q + 3], a3);
        b0 = fma2(v0.x, wb[4 * q + 0], b0);
        b1 = fma2(v0.y, wb[4 * q + 1], b1);
        b2 = fma2(v1.x, wb[4 * q + 2], b2);
        b3 = fma2(v1.y, wb[4 * q + 3], b3);
    }
    float2 ra = upk(add2(add2(a0, a1), add2(a2, a3)));
    float2 rb = upk(add2(add2(b0, b1), add2(b2, b3)));
    oa = ra.x + ra.y;
    ob = rb.x + rb.y;
}

#define LOAD_WROW(DST, SRC)                                                    \
    _Pragma("unroll")                                                          \
    for (int i = 0; i < 8; i++) {                                              \
        float4 v = *(const float4*)&(SRC)[lane * HH + 4 * i];                  \
        (DST)[2 * i] = pk(v.x, v.y);                                           \
        (DST)[2 * i + 1] = pk(v.z, v.w);                                       \
    }

// ============================================================================
// Kernel 1: z0 (verified: 95us). Transposed weight staging, conflict-free.
// ============================================================================
__global__ __launch_bounds__(256) void k_z0(const float* __restrict__ x,
                                            const float* __restrict__ Wih0,
                                            const float* __restrict__ bih0,
                                            const float* __restrict__ bhh0) {
    __shared__ __align__(16) float Xs[64 * EE];
    __shared__ float WsT[EE * 33];
    __shared__ float bs[HH];

    const int tid = threadIdx.x;
    const long R0 = (long)blockIdx.x * 64;

    {
        const float4* src = (const float4*)(x + R0 * EE);
        float4* dst = (float4*)Xs;
#pragma unroll
        for (int i = 0; i < 4; i++) dst[tid + 256 * i] = src[tid + 256 * i];
    }
    for (int i4 = tid; i4 < 512; i4 += 256) {
        float4 v = ((const float4*)Wih0)[i4];
        const int h = i4 >> 4;
        const int e0 = (i4 & 15) * 4;
        WsT[(e0 + 0) * 33 + h] = v.x;
        WsT[(e0 + 1) * 33 + h] = v.y;
        WsT[(e0 + 2) * 33 + h] = v.z;
        WsT[(e0 + 3) * 33 + h] = v.w;
    }
    if (tid < HH) bs[tid] = bih0[tid] + bhh0[tid];
    __syncthreads();

    const int h = tid & 31;
    const int rbase = tid >> 5;

    u64 wp[EE / 2];
#pragma unroll
    for (int k = 0; k < EE / 2; k++)
        wp[k] = pk(WsT[(2 * k) * 33 + h], WsT[(2 * k + 1) * 33 + h]);
    const float bias = bs[h];

#pragma unroll
    for (int rr = 0; rr < 8; rr++) {
        const int r = rbase + 8 * rr;
        u64 a = pk(bias, 0.0f), b = pk(0.0f, 0.0f);
#pragma unroll
        for (int e4 = 0; e4 < EE / 4; e4++) {
            ulonglong2 xv = *(const ulonglong2*)&Xs[r * EE + 4 * e4];  // bcast
            a = fma2(xv.x, wp[2 * e4 + 0], a);
            b = fma2(xv.y, wp[2 * e4 + 1], b);
        }
        float2 u = upk(add2(a, b));
        const long R = R0 + r;
        const int bidx = (int)(R >> 10);
        const int t = (int)(R & 1023);
        g_z0[((long)t * BB + bidx) * HH + h] = u.x + u.y;
    }
}

// ============================================================================
// Kernel 2: balanced producer/consumer scan.
//   producer (role 0): h0/t0 recurrence + d1 = bias1 + Wih1 . h0 (dual-dot on
//                      one LDS round); writes d1 into shared ring.
//   consumer (role 1): h1/t1 = tanh(d1 + Whh1 . h1_prev); writes ts1.
// r = w&3, role = w>>2  ->  each SMSP hosts one producer + one consumer.
// Chunked (16-step) flag handshake; all sync state block-local (graph-safe).
// ============================================================================
__global__ __launch_bounds__(256) void k_scan3(
    const float* __restrict__ eWhh0, const float* __restrict__ eWih1,
    const float* __restrict__ eWhh1, const float* __restrict__ ebih1,
    const float* __restrict__ ebhh1,
    const float* __restrict__ tWhh0, const float* __restrict__ tbih0,
    const float* __restrict__ tbhh0, const float* __restrict__ tWih1,
    const float* __restrict__ tWhh1, const float* __restrict__ tbih1,
    const float* __restrict__ tbhh1) {
    __shared__ __align__(16) float ring[4][NRING][CH][HH];  // 32 KB (d1 values)
    __shared__ __align__(16) float sA[4][2][HH];
    __shared__ __align__(16) float sB[4][2][HH];
    __shared__ volatile int prod[4];
    __shared__ volatile int cons[4];

    const int tid = threadIdx.x;
    const int lane = tid & 31;
    const int w = tid >> 5;
    const int r = w & 3;          // local row 0..3
    const int role = w >> 2;      // 0 = producer, 1 = consumer (mixed per SMSP)
    const int b = blockIdx.x * 4 + r;
    const int ST = BB * HH;

    if (tid < 4) { prod[tid] = 0; cons[tid] = 0; }
    __syncthreads();

    if (role == 0) {
        // ===================== producer =====================
        u64 w0p[16], wi1p[16];
        LOAD_WROW(w0p, eWhh0)
        LOAD_WROW(wi1p, eWih1)
        float bias1 = ebih1[lane] + ebhh1[lane];
        sA[r][0][lane] = 0.0f;
        WBAR();

        const float* zp = g_z0 + (long)b * HH + lane;
        float zbuf[8];
#pragma unroll
        for (int i = 0; i < 8; i++) zbuf[i] = zp[(long)i * ST];

        for (int k = 0; k < ENC_CHUNKS; k++) {
            if (k >= NRING) {
                while (cons[r] < k - (NRING - 1)) __nanosleep(32);
            }
            WBAR();
#pragma unroll
            for (int s = 0; s < CH; s++) {
                const int t = k * CH + s;
                const int cur = t & 1, nxt = cur ^ 1;
                const float zin = zbuf[s & 7];
                if (t + 8 < TT) zbuf[s & 7] = zp[(long)(t + 8) * ST];

                float o0, od1;
                dual_dot(w0p, wi1p, sA[r][cur], zin, bias1, o0, od1);
                const float h = ftanh(o0);           // h0[t]
                sA[r][nxt][lane] = h;
                if (t > 0) {                         // od1 = d1[t-1]
                    const int g = t - 1;
                    ring[r][(g >> 4) & (NRING - 1)][g & 15][lane] = od1;
                    if (s == 0) {                    // chunk k-1 now complete
                        __threadfence_block();
                        __syncwarp();
                        if (lane == 0) prod[r] = k;
                    }
                }
                WBAR();
            }
        }
        // epilogue: d1[TT-1] from sA[0] (TT even)
        {
            const float od1 = dot32w(wi1p, sA[r][0], bias1);
            const int g = TT - 1;
            ring[r][(g >> 4) & (NRING - 1)][g & 15][lane] = od1;
            __threadfence_block();
            __syncwarp();
            if (lane == 0) prod[r] = ENC_CHUNKS;
        }

        // -------- transition (sA[0] already holds hT0 = h0[TT-1]) --------
        LOAD_WROW(w0p, tWhh0)
        LOAD_WROW(wi1p, tWih1)
        const float bias0 = tbih0[lane] + tbhh0[lane];
        bias1 = tbih1[lane] + tbhh1[lane];

        for (int k = 0; k < TRA_CHUNKS; k++) {
            const int gk = ENC_CHUNKS + k;
            while (cons[r] < gk - (NRING - 1)) __nanosleep(32);
            WBAR();
#pragma unroll
            for (int s = 0; s < CH; s++) {
                const int p = k * CH + s;
                const int cur = p & 1, nxt = cur ^ 1;

                float o0, od1;
                dual_dot(w0p, wi1p, sA[r][cur], bias0, bias1, o0, od1);
                const float h = ftanh(o0);           // t0[p]
                sA[r][nxt][lane] = h;
                if (p > 0) {                         // od1 = d1[p-1]
                    const int g = TT + p - 1;
                    ring[r][(g >> 4) & (NRING - 1)][g & 15][lane] = od1;
                    if (s == 0) {
                        __threadfence_block();
                        __syncwarp();
                        if (lane == 0) prod[r] = gk;
                    }
                }
                WBAR();
            }
        }
        // epilogue: d1[PP-1] from sA[0] (PP even)
        {
            const float od1 = dot32w(wi1p, sA[r][0], bias1);
            const int g = TT + PP - 1;
            ring[r][(g >> 4) & (NRING - 1)][g & 15][lane] = od1;
            __threadfence_block();
            __syncwarp();
            if (lane == 0) prod[r] = ENC_CHUNKS + TRA_CHUNKS;
        }
    } else {
        // ===================== consumer =====================
        u64 whp[16];
        LOAD_WROW(whp, eWhh1)
        sB[r][0][lane] = 0.0f;
        WBAR();

        float h1 = 0.0f;
        for (int k = 0; k < ENC_CHUNKS; k++) {
            while (prod[r] < k + 1) __nanosleep(32);
            __threadfence_block();
            WBAR();
#pragma unroll
            for (int s = 0; s < CH; s++) {
                const int t = k * CH + s;
                const int cur = t & 1, nxt = cur ^ 1;
                const float d1 = ring[r][k & (NRING - 1)][s][lane];
                const float d2 = dot32w(whp, sB[r][cur], 0.0f);
                h1 = ftanh(d1 + d2);                 // h1[t]
                sB[r][nxt][lane] = h1;
                WBAR();
            }
            __syncwarp();
            if (lane == 0) cons[r] = k + 1;
        }
        // sB[0] holds hT1 = h1[TT-1] (TT even)

        LOAD_WROW(whp, tWhh1)
        float* tp = g_ts1 + (long)b * HH + lane;

        for (int k = 0; k < TRA_CHUNKS; k++) {
            const int gk = ENC_CHUNKS + k;
            while (prod[r] < gk + 1) __nanosleep(32);
            __threadfence_block();
            WBAR();
#pragma unroll
            for (int s = 0; s < CH; s++) {
                const int p = k * CH + s;
                const int cur = p & 1, nxt = cur ^ 1;
                const float d1 = ring[r][gk & (NRING - 1)][s][lane];
                const float d2 = dot32w(whp, sB[r][cur], 0.0f);
                h1 = ftanh(d1 + d2);                 // t1[p]
                tp[(long)p * ST] = h1;
                sB[r][nxt][lane] = h1;
                WBAR();
            }
            __syncwarp();
            if (lane == 0) cons[r] = gk + 1;
        }
    }
}

// ============================================================================
// Kernel 3: observation MLP (verified: 137us). 128-row tile,
// launch_bounds(256,2), fast gelu.
// ============================================================================
#define MLP_SMEM_FLOATS (4096 + 2304 + 4352 + 8192 + 128)

__global__ __launch_bounds__(256, 2) void k_mlp(const float* __restrict__ W1,
                                                const float* __restrict__ b1,
                                                const float* __restrict__ W2,
                                                const float* __restrict__ b2,
                                                float* __restrict__ out) {
    extern __shared__ __align__(16) float sm[];
    float* Xs  = sm;                  // [128][32]
    float* W1s = sm + 4096;           // [64][36]
    float* W2s = sm + 6400;           // [64][68]
    float* Gs  = sm + 10752;          // [128][64]
    float* b1s = sm + 18944;
    float* b2s = sm + 19008;

    const int tid = threadIdx.x;
    const int tx = tid & 15;          // col: e_j = tx + 16*j
    const int ty = tid >> 4;          // rows 8*ty .. 8*ty+7
    const int p0 = blockIdx.x * 16;
    const int b0 = blockIdx.y * 8;

    for (int i4 = tid; i4 < 1024; i4 += 256) {
        const int r = i4 >> 3, c4 = i4 & 7;
        const int bl = r >> 4, pl = r & 15;
        ((float4*)Xs)[i4] =
            *(const float4*)&g_ts1[((long)(p0 + pl) * BB + (b0 + bl)) * HH + 4 * c4];
    }
    for (int i4 = tid; i4 < 512; i4 += 256) {
        const int j = i4 >> 3, k4 = i4 & 7;
        ((float4*)W1s)[j * 9 + k4] = ((const float4*)W1)[i4];
    }
    for (int i4 = tid; i4 < 1024; i4 += 256) {
        const int e = i4 >> 4, j4 = i4 & 15;
        ((float4*)W2s)[e * 17 + j4] = ((const float4*)W2)[i4];
    }
    if (tid < 64) b1s[tid] = b1[tid];
    else if (tid < 128) b2s[tid - 64] = b2[tid - 64];
    __syncthreads();

    u64 acc[8][4];
#pragma unroll
    for (int i = 0; i < 8; i++)
#pragma unroll
        for (int j = 0; j < 4; j++) acc[i][j] = pk(b1s[tx + 16 * j], 0.0f);

#pragma unroll
    for (int k4 = 0; k4 < 8; k4++) {
        ulonglong2 wv[4];
#pragma unroll
        for (int j = 0; j < 4; j++)
            wv[j] = *(const ulonglong2*)&W1s[(tx + 16 * j) * 36 + 4 * k4];
#pragma unroll
        for (int i = 0; i < 8; i++) {
            ulonglong2 xv = *(const ulonglong2*)&Xs[(8 * ty + i) * 32 + 4 * k4];
#pragma unroll
            for (int j = 0; j < 4; j++) {
                acc[i][j] = fma2(xv.x, wv[j].x, acc[i][j]);
                acc[i][j] = fma2(xv.y, wv[j].y, acc[i][j]);
            }
        }
    }

#pragma unroll
    for (int i = 0; i < 8; i++) {
#pragma unroll
        for (int j = 0; j < 4; j++) {
            float2 uj = upk(acc[i][j]);
            Gs[(8 * ty + i) * 64 + tx + 16 * j] = gelu(uj.x + uj.y);
        }
    }
    __syncthreads();

#pragma unroll
    for (int i = 0; i < 8; i++)
#pragma unroll
        for (int j = 0; j < 4; j++) acc[i][j] = pk(b2s[tx + 16 * j], 0.0f);

#pragma unroll
    for (int k4 = 0; k4 < 16; k4++) {
        ulonglong2 wv[4];
#pragma unroll
        for (int j = 0; j < 4; j++)
            wv[j] = *(const ulonglong2*)&W2s[(tx + 16 * j) * 68 + 4 * k4];
#pragma unroll
        for (int i = 0; i < 8; i++) {
            ulonglong2 gv = *(const ulonglong2*)&Gs[(8 * ty + i) * 64 + 4 * k4];
#pragma unroll
            for (int j = 0; j < 4; j++) {
                acc[i][j] = fma2(gv.x, wv[j].x, acc[i][j]);
                acc[i][j] = fma2(gv.y, wv[j].y, acc[i][j]);
            }
        }
    }

    float y[8][4];
#pragma unroll
    for (int i = 0; i < 8; i++)
#pragma unroll
        for (int j = 0; j < 4; j++) {
            float2 uj = upk(acc[i][j]);
            y[i][j] = uj.x + uj.y;
        }

    const int bl = ty >> 1;
    const int plb = (ty & 1) * 8;
    float* ob = out + (long)(b0 + bl) * EE * PP + p0 + plb;
#pragma unroll
    for (int j = 0; j < 4; j++) {
        const int e = tx + 16 * j;
#pragma unroll
        for (int q = 0; q < 2; q++) {
            float4 v;
            v.x = y[4 * q + 0][j]; v.y = y[4 * q + 1][j];
            v.z = y[4 * q + 2][j]; v.w = y[4 * q + 3][j];
            *(float4*)&ob[(long)e * PP + 4 * q] = v;
        }
    }
}

// ============================================================================
extern "C" void kernel_launch(void* const* d_in, const int* in_sizes, int n_in,
                              void* d_out, int out_size) {
    (void)in_sizes; (void)n_in; (void)out_size;
    const float* x      = (const float*)d_in[0];
    const float* e_Wih0 = (const float*)d_in[1];
    const float* e_Whh0 = (const float*)d_in[2];
    const float* e_bih0 = (const float*)d_in[3];
    const float* e_bhh0 = (const float*)d_in[4];
    const float* e_Wih1 = (const float*)d_in[5];
    const float* e_Whh1 = (const float*)d_in[6];
    const float* e_bih1 = (const float*)d_in[7];
    const float* e_bhh1 = (const float*)d_in[8];
    // d_in[9] = t_Wih0: unused (transition input is zeros)
    const float* t_Whh0 = (const float*)d_in[10];
    const float* t_bih0 = (const float*)d_in[11];
    const float* t_bhh0 = (const float*)d_in[12];
    const float* t_Wih1 = (const float*)d_in[13];
    const float* t_Whh1 = (const float*)d_in[14];
    const float* t_bih1 = (const float*)d_in[15];
    const float* t_bhh1 = (const float*)d_in[16];
    const float* o_W1   = (const float*)d_in[17];
    const float* o_b1   = (const float*)d_in[18];
    const float* o_W2   = (const float*)d_in[19];
    const float* o_b2   = (const float*)d_in[20];
    float* out = (float*)d_out;

    cudaFuncSetAttribute(k_mlp, cudaFuncAttributeMaxDynamicSharedMemorySize,
                         MLP_SMEM_FLOATS * 4);

    k_z0<<<(BB * TT) / 64, 256>>>(x, e_Wih0, e_bih0, e_bhh0);
    k_scan3<<<BB / 4, 256>>>(e_Whh0, e_Wih1, e_Whh1, e_bih1, e_bhh1,
                             t_Whh0, t_bih0, t_bhh0, t_Wih1, t_Whh1,
                             t_bih1, t_bhh1);
    dim3 g(PP / 16, BB / 8);
    k_mlp<<<g, 256, MLP_SMEM_FLOATS * 4>>>(o_W1, o_b1, o_W2, o_b2, out);
}

// round 15
// speedup vs baseline: 1.1531x; 1.1531x over previous
#include <cuda_runtime.h>
#include <math.h>

#define BB 512
#define TT 1024
#define EE 64
#define HH 32
#define PP 720

#define CH 16                       // steps per ring chunk
#define NRING 4                     // ring depth (chunks)
#define ENC_CHUNKS (TT / CH)        // 64
#define TRA_CHUNKS (PP / CH)        // 45

typedef unsigned long long u64;

// ---------------- scratch (device globals: no allocation allowed) ----------
__device__ float g_z0[(size_t)TT * BB * HH];   // [t][b][h]
__device__ float g_ts1[(size_t)PP * BB * HH];  // [p][b][h]

#define WBAR() asm volatile("" ::: "memory")

// ---------------- packed fp32x2 helpers (Blackwell FFMA2) ------------------
__device__ __forceinline__ u64 pk(float a, float b) {
    u64 r; asm("mov.b64 %0, {%1,%2};" : "=l"(r) : "f"(a), "f"(b)); return r;
}
__device__ __forceinline__ float2 upk(u64 v) {
    float2 r; asm("mov.b64 {%0,%1}, %2;" : "=f"(r.x), "=f"(r.y) : "l"(v)); return r;
}
__device__ __forceinline__ u64 fma2(u64 a, u64 b, u64 c) {
    u64 d; asm("fma.rn.f32x2 %0, %1, %2, %3;" : "=l"(d) : "l"(a), "l"(b), "l"(c)); return d;
}
__device__ __forceinline__ u64 add2(u64 a, u64 b) {
    u64 d; asm("add.rn.f32x2 %0, %1, %2;" : "=l"(d) : "l"(a), "l"(b)); return d;
}

// fast tanh: tanh(x) = 1 - 2/(1+exp(2x)); exact at both saturations.
__device__ __forceinline__ float ftanh(float x) {
    float e;
    asm("ex2.approx.f32 %0, %1;" : "=f"(e) : "f"(x * 2.885390081777927f));
    return 1.0f - __fdividef(2.0f, e + 1.0f);
}

// exact-GELU via Abramowitz-Stegun 7.1.26 erf (abs err <= 1.5e-7).
__device__ __forceinline__ float gelu(float x) {
    const float u = x * 0.70710678118654752f;
    const float au = fabsf(u);
    const float t = __fdividef(1.0f, fmaf(0.3275911f, au, 1.0f));
    const float e = __expf(-u * u);
    float p = fmaf(t, 1.061405429f, -1.453152027f);
    p = fmaf(t, p, 1.421413741f);
    p = fmaf(t, p, -0.284496736f);
    p = fmaf(t, p, 0.254829592f);
    const float erf_abs = fmaf(-p * t, e, 1.0f);
    const float er = copysignf(erf_abs, u);
    return 0.5f * x * (1.0f + er);
}

// dot(32-float shared vector, packed weight row) + init; 4 split chains
__device__ __forceinline__ float dot32w(const u64* wp,
                                        const float* __restrict__ sh,
                                        float init) {
    const u64 ZZ = pk(0.0f, 0.0f);
    u64 a = pk(init, 0.0f), b = ZZ, c = ZZ, d = ZZ;
#pragma unroll
    for (int q = 0; q < 4; q++) {
        ulonglong2 v0 = *(const ulonglong2*)&sh[8 * q];
        ulonglong2 v1 = *(const ulonglong2*)&sh[8 * q + 4];
        a = fma2(v0.x, wp[4 * q + 0], a);
        b = fma2(v0.y, wp[4 * q + 1], b);
        c = fma2(v1.x, wp[4 * q + 2], c);
        d = fma2(v1.y, wp[4 * q + 3], d);
    }
    float2 r = upk(add2(add2(a, b), add2(c, d)));
    return r.x + r.y;
}

#define LOAD_WROW(DST, SRC)                                                    \
    _Pragma("unroll")                                                          \
    for (int i = 0; i < 8; i++) {                                              \
        float4 v = *(const float4*)&(SRC)[lane * HH + 4 * i];                  \
        (DST)[2 * i] = pk(v.x, v.y);                                           \
        (DST)[2 * i + 1] = pk(v.z, v.w);                                       \
    }

// ============================================================================
// Kernel 1: z0 (verified: 95us). Transposed weight staging, conflict-free.
// ============================================================================
__global__ __launch_bounds__(256) void k_z0(const float* __restrict__ x,
                                            const float* __restrict__ Wih0,
                                            const float* __restrict__ bih0,
                                            const float* __restrict__ bhh0) {
    __shared__ __align__(16) float Xs[64 * EE];
    __shared__ float WsT[EE * 33];
    __shared__ float bs[HH];

    const int tid = threadIdx.x;
    const long R0 = (long)blockIdx.x * 64;

    {
        const float4* src = (const float4*)(x + R0 * EE);
        float4* dst = (float4*)Xs;
#pragma unroll
        for (int i = 0; i < 4; i++) dst[tid + 256 * i] = src[tid + 256 * i];
    }
    for (int i4 = tid; i4 < 512; i4 += 256) {
        float4 v = ((const float4*)Wih0)[i4];
        const int h = i4 >> 4;
        const int e0 = (i4 & 15) * 4;
        WsT[(e0 + 0) * 33 + h] = v.x;
        WsT[(e0 + 1) * 33 + h] = v.y;
        WsT[(e0 + 2) * 33 + h] = v.z;
        WsT[(e0 + 3) * 33 + h] = v.w;
    }
    if (tid < HH) bs[tid] = bih0[tid] + bhh0[tid];
    __syncthreads();

    const int h = tid & 31;
    const int rbase = tid >> 5;

    u64 wp[EE / 2];
#pragma unroll
    for (int k = 0; k < EE / 2; k++)
        wp[k] = pk(WsT[(2 * k) * 33 + h], WsT[(2 * k + 1) * 33 + h]);
    const float bias = bs[h];

#pragma unroll
    for (int rr = 0; rr < 8; rr++) {
        const int r = rbase + 8 * rr;
        u64 a = pk(bias, 0.0f), b = pk(0.0f, 0.0f);
#pragma unroll
        for (int e4 = 0; e4 < EE / 4; e4++) {
            ulonglong2 xv = *(const ulonglong2*)&Xs[r * EE + 4 * e4];  // bcast
            a = fma2(xv.x, wp[2 * e4 + 0], a);
            b = fma2(xv.y, wp[2 * e4 + 1], b);
        }
        float2 u = upk(add2(a, b));
        const long R = R0 + r;
        const int bidx = (int)(R >> 10);
        const int t = (int)(R & 1023);
        g_z0[((long)t * BB + bidx) * HH + h] = u.x + u.y;
    }
}

// ============================================================================
// Kernel 2: producer/consumer scan (R13 math verbatim). ONLY change vs R13:
// warp mapping r = w&3, role = w>>2 -> each SMSP (w mod 4) hosts one producer
// AND one consumer (was role-pure SMSPs: consumers at 2x110 issue-cyc bound).
//   warp role 0 (A): layer-0 recurrence, writes h0/t0 chunks into shared ring
//   warp role 1 (B): layer-1 recurrence, reads ring, writes ts1 (transition)
// ============================================================================
__global__ __launch_bounds__(256) void k_scan2(
    const float* __restrict__ eWhh0, const float* __restrict__ eWih1,
    const float* __restrict__ eWhh1, const float* __restrict__ ebih1,
    const float* __restrict__ ebhh1,
    const float* __restrict__ tWhh0, const float* __restrict__ tbih0,
    const float* __restrict__ tbhh0, const float* __restrict__ tWih1,
    const float* __restrict__ tWhh1, const float* __restrict__ tbih1,
    const float* __restrict__ tbhh1) {
    __shared__ __align__(16) float ring[4][NRING][CH][HH];  // 32 KB
    __shared__ __align__(16) float sA[4][2][HH];
    __shared__ __align__(16) float sB[4][2][HH];
    __shared__ volatile int prod[4];
    __shared__ volatile int cons[4];

    const int tid = threadIdx.x;
    const int lane = tid & 31;
    const int w = tid >> 5;
    const int r = w & 3;          // local row 0..3   (CHANGED: was w>>1)
    const int role = w >> 2;      // 0 = producer, 1 = consumer (CHANGED: was w&1)
    const int b = blockIdx.x * 4 + r;
    const int ST = BB * HH;

    if (tid < 4) { prod[tid] = 0; cons[tid] = 0; }
    __syncthreads();

    if (role == 0) {
        // ================= producer: layer-0 chains =================
        u64 wp[16];
        LOAD_WROW(wp, eWhh0)
        sA[r][0][lane] = 0.0f;
        WBAR();

        const float* zp = g_z0 + (long)b * HH + lane;
        float zbuf[8];
#pragma unroll
        for (int i = 0; i < 8; i++) zbuf[i] = zp[(long)i * ST];

        float h = 0.0f;
        for (int k = 0; k < ENC_CHUNKS; k++) {
            if (k >= NRING) {
                while (cons[r] < k - (NRING - 1)) __nanosleep(32);
            }
            WBAR();
            float* slot = (float*)&ring[r][k & (NRING - 1)][0][0];
#pragma unroll
            for (int s = 0; s < CH; s++) {
                const int t = k * CH + s;
                const int cur = t & 1, nxt = cur ^ 1;
                const float zin = zbuf[t & 7];
                if (t + 8 < TT) zbuf[t & 7] = zp[(long)(t + 8) * ST];
                h = ftanh(dot32w(wp, sA[r][cur], zin));
                sA[r][nxt][lane] = h;
                slot[s * HH + lane] = h;
                WBAR();
            }
            __threadfence_block();
            __syncwarp();
            if (lane == 0) prod[r] = k + 1;
        }
        const float hT0 = h;

        // transition layer 0: t0[p] = tanh(bias0 + Whh0 . t0[p-1])
        LOAD_WROW(wp, tWhh0)
        const float bias0 = tbih0[lane] + tbhh0[lane];
        sA[r][0][lane] = hT0;
        WBAR();

        for (int k = 0; k < TRA_CHUNKS; k++) {
            const int gk = ENC_CHUNKS + k;
            while (cons[r] < gk - (NRING - 1)) __nanosleep(32);
            WBAR();
            float* slot = (float*)&ring[r][gk & (NRING - 1)][0][0];
#pragma unroll
            for (int s = 0; s < CH; s++) {
                const int p = k * CH + s;
                const int cur = p & 1, nxt = cur ^ 1;
                h = ftanh(dot32w(wp, sA[r][cur], bias0));
                sA[r][nxt][lane] = h;
                slot[s * HH + lane] = h;
                WBAR();
            }
            __threadfence_block();
            __syncwarp();
            if (lane == 0) prod[r] = gk + 1;
        }
    } else {
        // ================= consumer: layer-1 chains =================
        u64 wip[16], whp[16];
        LOAD_WROW(wip, eWih1)
        LOAD_WROW(whp, eWhh1)
        float bias1 = ebih1[lane] + ebhh1[lane];
        sB[r][0][lane] = 0.0f;
        WBAR();

        float h1 = 0.0f;
        for (int k = 0; k < ENC_CHUNKS; k++) {
            while (prod[r] < k + 1) __nanosleep(32);
            __threadfence_block();
            WBAR();
            const float* slot = (const float*)&ring[r][k & (NRING - 1)][0][0];
#pragma unroll
            for (int s = 0; s < CH; s++) {
                const int t = k * CH + s;
                const int cur = t & 1, nxt = cur ^ 1;
                const float d1 = dot32w(wip, &slot[s * HH], bias1);
                const float d2 = dot32w(whp, sB[r][cur], 0.0f);
                h1 = ftanh(d1 + d2);
                sB[r][nxt][lane] = h1;
                WBAR();
            }
            __threadfence_block();
            __syncwarp();
            if (lane == 0) cons[r] = k + 1;
        }
        const float hT1 = h1;

        // transition layer 1: t1[p] = tanh(bias1 + Wih1 . t0[p] + Whh1 . t1[p-1])
        LOAD_WROW(wip, tWih1)
        LOAD_WROW(whp, tWhh1)
        bias1 = tbih1[lane] + tbhh1[lane];
        sB[r][0][lane] = hT1;
        WBAR();

        float* tp = g_ts1 + (long)b * HH + lane;
        for (int k = 0; k < TRA_CHUNKS; k++) {
            const int gk = ENC_CHUNKS + k;
            while (prod[r] < gk + 1) __nanosleep(32);
            __threadfence_block();
            WBAR();
            const float* slot = (const float*)&ring[r][gk & (NRING - 1)][0][0];
#pragma unroll
            for (int s = 0; s < CH; s++) {
                const int p = k * CH + s;
                const int cur = p & 1, nxt = cur ^ 1;
                const float d1 = dot32w(wip, &slot[s * HH], bias1);
                const float d2 = dot32w(whp, sB[r][cur], 0.0f);
                h1 = ftanh(d1 + d2);
                tp[(long)p * ST] = h1;
                sB[r][nxt][lane] = h1;
                WBAR();
            }
            __threadfence_block();
            __syncwarp();
            if (lane == 0) cons[r] = gk + 1;
        }
    }
}

// ============================================================================
// Kernel 3: observation MLP (verified: 137us). 128-row tile,
// launch_bounds(256,2), fast gelu.
// ============================================================================
#define MLP_SMEM_FLOATS (4096 + 2304 + 4352 + 8192 + 128)

__global__ __launch_bounds__(256, 2) void k_mlp(const float* __restrict__ W1,
                                                const float* __restrict__ b1,
                                                const float* __restrict__ W2,
                                                const float* __restrict__ b2,
                                                float* __restrict__ out) {
    extern __shared__ __align__(16) float sm[];
    float* Xs  = sm;                  // [128][32]
    float* W1s = sm + 4096;           // [64][36]
    float* W2s = sm + 6400;           // [64][68]
    float* Gs  = sm + 10752;          // [128][64]
    float* b1s = sm + 18944;
    float* b2s = sm + 19008;

    const int tid = threadIdx.x;
    const int tx = tid & 15;          // col: e_j = tx + 16*j
    const int ty = tid >> 4;          // rows 8*ty .. 8*ty+7
    const int p0 = blockIdx.x * 16;
    const int b0 = blockIdx.y * 8;

    for (int i4 = tid; i4 < 1024; i4 += 256) {
        const int r = i4 >> 3, c4 = i4 & 7;
        const int bl = r >> 4, pl = r & 15;
        ((float4*)Xs)[i4] =
            *(const float4*)&g_ts1[((long)(p0 + pl) * BB + (b0 + bl)) * HH + 4 * c4];
    }
    for (int i4 = tid; i4 < 512; i4 += 256) {
        const int j = i4 >> 3, k4 = i4 & 7;
        ((float4*)W1s)[j * 9 + k4] = ((const float4*)W1)[i4];
    }
    for (int i4 = tid; i4 < 1024; i4 += 256) {
        const int e = i4 >> 4, j4 = i4 & 15;
        ((float4*)W2s)[e * 17 + j4] = ((const float4*)W2)[i4];
    }
    if (tid < 64) b1s[tid] = b1[tid];
    else if (tid < 128) b2s[tid - 64] = b2[tid - 64];
    __syncthreads();

    u64 acc[8][4];
#pragma unroll
    for (int i = 0; i < 8; i++)
#pragma unroll
        for (int j = 0; j < 4; j++) acc[i][j] = pk(b1s[tx + 16 * j], 0.0f);

#pragma unroll
    for (int k4 = 0; k4 < 8; k4++) {
        ulonglong2 wv[4];
#pragma unroll
        for (int j = 0; j < 4; j++)
            wv[j] = *(const ulonglong2*)&W1s[(tx + 16 * j) * 36 + 4 * k4];
#pragma unroll
        for (int i = 0; i < 8; i++) {
            ulonglong2 xv = *(const ulonglong2*)&Xs[(8 * ty + i) * 32 + 4 * k4];
#pragma unroll
            for (int j = 0; j < 4; j++) {
                acc[i][j] = fma2(xv.x, wv[j].x, acc[i][j]);
                acc[i][j] = fma2(xv.y, wv[j].y, acc[i][j]);
            }
        }
    }

#pragma unroll
    for (int i = 0; i < 8; i++) {
#pragma unroll
        for (int j = 0; j < 4; j++) {
            float2 uj = upk(acc[i][j]);
            Gs[(8 * ty + i) * 64 + tx + 16 * j] = gelu(uj.x + uj.y);
        }
    }
    __syncthreads();

#pragma unroll
    for (int i = 0; i < 8; i++)
#pragma unroll
        for (int j = 0; j < 4; j++) acc[i][j] = pk(b2s[tx + 16 * j], 0.0f);

#pragma unroll
    for (int k4 = 0; k4 < 16; k4++) {
        ulonglong2 wv[4];
#pragma unroll
        for (int j = 0; j < 4; j++)
            wv[j] = *(const ulonglong2*)&W2s[(tx + 16 * j) * 68 + 4 * k4];
#pragma unroll
        for (int i = 0; i < 8; i++) {
            ulonglong2 gv = *(const ulonglong2*)&Gs[(8 * ty + i) * 64 + 4 * k4];
#pragma unroll
            for (int j = 0; j < 4; j++) {
                acc[i][j] = fma2(gv.x, wv[j].x, acc[i][j]);
                acc[i][j] = fma2(gv.y, wv[j].y, acc[i][j]);
            }
        }
    }

    float y[8][4];
#pragma unroll
    for (int i = 0; i < 8; i++)
#pragma unroll
        for (int j = 0; j < 4; j++) {
            float2 uj = upk(acc[i][j]);
            y[i][j] = uj.x + uj.y;
        }

    const int bl = ty >> 1;
    const int plb = (ty & 1) * 8;
    float* ob = out + (long)(b0 + bl) * EE * PP + p0 + plb;
#pragma unroll
    for (int j = 0; j < 4; j++) {
        const int e = tx + 16 * j;
#pragma unroll
        for (int q = 0; q < 2; q++) {
            float4 v;
            v.x = y[4 * q + 0][j]; v.y = y[4 * q + 1][j];
            v.z = y[4 * q + 2][j]; v.w = y[4 * q + 3][j];
            *(float4*)&ob[(long)e * PP + 4 * q] = v;
        }
    }
}

// ============================================================================
extern "C" void kernel_launch(void* const* d_in, const int* in_sizes, int n_in,
                              void* d_out, int out_size) {
    (void)in_sizes; (void)n_in; (void)out_size;
    const float* x      = (const float*)d_in[0];
    const float* e_Wih0 = (const float*)d_in[1];
    const float* e_Whh0 = (const float*)d_in[2];
    const float* e_bih0 = (const float*)d_in[3];
    const float* e_bhh0 = (const float*)d_in[4];
    const float* e_Wih1 = (const float*)d_in[5];
    const float* e_Whh1 = (const float*)d_in[6];
    const float* e_bih1 = (const float*)d_in[7];
    const float* e_bhh1 = (const float*)d_in[8];
    // d_in[9] = t_Wih0: unused (transition input is zeros)
    const float* t_Whh0 = (const float*)d_in[10];
    const float* t_bih0 = (const float*)d_in[11];
    const float* t_bhh0 = (const float*)d_in[12];
    const float* t_Wih1 = (const float*)d_in[13];
    const float* t_Whh1 = (const float*)d_in[14];
    const float* t_bih1 = (const float*)d_in[15];
    const float* t_bhh1 = (const float*)d_in[16];
    const float* o_W1   = (const float*)d_in[17];
    const float* o_b1   = (const float*)d_in[18];
    const float* o_W2   = (const float*)d_in[19];
    const float* o_b2   = (const float*)d_in[20];
    float* out = (float*)d_out;

    cudaFuncSetAttribute(k_mlp, cudaFuncAttributeMaxDynamicSharedMemorySize,
                         MLP_SMEM_FLOATS * 4);

    k_z0<<<(BB * TT) / 64, 256>>>(x, e_Wih0, e_bih0, e_bhh0);
    k_scan2<<<BB / 4, 256>>>(e_Whh0, e_Wih1, e_Whh1, e_bih1, e_bhh1,
                             t_Whh0, t_bih0, t_bhh0, t_Wih1, t_Whh1,
                             t_bih1, t_bhh1);
    dim3 g(PP / 16, BB / 8);
    k_mlp<<<g, 256, MLP_SMEM_FLOATS * 4>>>(o_W1, o_b1, o_W2, o_b2, out);
}

// round 16
// speedup vs baseline: 1.2603x; 1.0930x over previous
#include <cuda_runtime.h>
#include <math.h>

#define BB 512
#define TT 1024
#define EE 64
#define HH 32
#define PP 720

#define CH 8                        // steps per ring chunk
#define NRING 8                     // ring depth (chunks)
#define ENC_CHUNKS (TT / CH)        // 128
#define TRA_CHUNKS (PP / CH)        // 90

typedef unsigned long long u64;

// ---------------- scratch (device globals: no allocation allowed) ----------
__device__ float g_z0[(size_t)TT * BB * HH];   // [t][b][h]
__device__ float g_ts1[(size_t)PP * BB * HH];  // [p][b][h]

#define WBAR() asm volatile("" ::: "memory")

// ---------------- packed fp32x2 helpers (Blackwell FFMA2) ------------------
__device__ __forceinline__ u64 pk(float a, float b) {
    u64 r; asm("mov.b64 %0, {%1,%2};" : "=l"(r) : "f"(a), "f"(b)); return r;
}
__device__ __forceinline__ float2 upk(u64 v) {
    float2 r; asm("mov.b64 {%0,%1}, %2;" : "=f"(r.x), "=f"(r.y) : "l"(v)); return r;
}
__device__ __forceinline__ u64 fma2(u64 a, u64 b, u64 c) {
    u64 d; asm("fma.rn.f32x2 %0, %1, %2, %3;" : "=l"(d) : "l"(a), "l"(b), "l"(c)); return d;
}
__device__ __forceinline__ u64 add2(u64 a, u64 b) {
    u64 d; asm("add.rn.f32x2 %0, %1, %2;" : "=l"(d) : "l"(a), "l"(b)); return d;
}

// hardware tanh (MUFU.TANH): single 16-cyc MUFU, abs err ~5e-4.
// Evidence-based: measured error gain through the recurrence is < 1
// (ftanh err 1e-6 -> final rel_err 2.3e-7), so expect final ~1e-4 << 1e-3.
__device__ __forceinline__ float ftanh(float x) {
    float r; asm("tanh.approx.f32 %0, %1;" : "=f"(r) : "f"(x)); return r;
}

// exact-GELU via Abramowitz-Stegun 7.1.26 erf (abs err <= 1.5e-7).
__device__ __forceinline__ float gelu(float x) {
    const float u = x * 0.70710678118654752f;
    const float au = fabsf(u);
    const float t = __fdividef(1.0f, fmaf(0.3275911f, au, 1.0f));
    const float e = __expf(-u * u);
    float p = fmaf(t, 1.061405429f, -1.453152027f);
    p = fmaf(t, p, 1.421413741f);
    p = fmaf(t, p, -0.284496736f);
    p = fmaf(t, p, 0.254829592f);
    const float erf_abs = fmaf(-p * t, e, 1.0f);
    const float er = copysignf(erf_abs, u);
    return 0.5f * x * (1.0f + er);
}

// dot(32-float shared vector, packed weight row) + init; 4 split chains
__device__ __forceinline__ float dot32w(const u64* wp,
                                        const float* __restrict__ sh,
                                        float init) {
    const u64 ZZ = pk(0.0f, 0.0f);
    u64 a = pk(init, 0.0f), b = ZZ, c = ZZ, d = ZZ;
#pragma unroll
    for (int q = 0; q < 4; q++) {
        ulonglong2 v0 = *(const ulonglong2*)&sh[8 * q];
        ulonglong2 v1 = *(const ulonglong2*)&sh[8 * q + 4];
        a = fma2(v0.x, wp[4 * q + 0], a);
        b = fma2(v0.y, wp[4 * q + 1], b);
        c = fma2(v1.x, wp[4 * q + 2], c);
        d = fma2(v1.y, wp[4 * q + 3], d);
    }
    float2 r = upk(add2(add2(a, b), add2(c, d)));
    return r.x + r.y;
}

#define LOAD_WROW(DST, SRC)                                                    \
    _Pragma("unroll")                                                          \
    for (int i = 0; i < 8; i++) {                                              \
        float4 v = *(const float4*)&(SRC)[lane * HH + 4 * i];                  \
        (DST)[2 * i] = pk(v.x, v.y);                                           \
        (DST)[2 * i + 1] = pk(v.z, v.w);                                       \
    }

// ============================================================================
// Kernel 1: z0 (verified: 95us). Transposed weight staging, conflict-free.
// ============================================================================
__global__ __launch_bounds__(256) void k_z0(const float* __restrict__ x,
                                            const float* __restrict__ Wih0,
                                            const float* __restrict__ bih0,
                                            const float* __restrict__ bhh0) {
    __shared__ __align__(16) float Xs[64 * EE];
    __shared__ float WsT[EE * 33];
    __shared__ float bs[HH];

    const int tid = threadIdx.x;
    const long R0 = (long)blockIdx.x * 64;

    {
        const float4* src = (const float4*)(x + R0 * EE);
        float4* dst = (float4*)Xs;
#pragma unroll
        for (int i = 0; i < 4; i++) dst[tid + 256 * i] = src[tid + 256 * i];
    }
    for (int i4 = tid; i4 < 512; i4 += 256) {
        float4 v = ((const float4*)Wih0)[i4];
        const int h = i4 >> 4;
        const int e0 = (i4 & 15) * 4;
        WsT[(e0 + 0) * 33 + h] = v.x;
        WsT[(e0 + 1) * 33 + h] = v.y;
        WsT[(e0 + 2) * 33 + h] = v.z;
        WsT[(e0 + 3) * 33 + h] = v.w;
    }
    if (tid < HH) bs[tid] = bih0[tid] + bhh0[tid];
    __syncthreads();

    const int h = tid & 31;
    const int rbase = tid >> 5;

    u64 wp[EE / 2];
#pragma unroll
    for (int k = 0; k < EE / 2; k++)
        wp[k] = pk(WsT[(2 * k) * 33 + h], WsT[(2 * k + 1) * 33 + h]);
    const float bias = bs[h];

#pragma unroll
    for (int rr = 0; rr < 8; rr++) {
        const int r = rbase + 8 * rr;
        u64 a = pk(bias, 0.0f), b = pk(0.0f, 0.0f);
#pragma unroll
        for (int e4 = 0; e4 < EE / 4; e4++) {
            ulonglong2 xv = *(const ulonglong2*)&Xs[r * EE + 4 * e4];  // bcast
            a = fma2(xv.x, wp[2 * e4 + 0], a);
            b = fma2(xv.y, wp[2 * e4 + 1], b);
        }
        float2 u = upk(add2(a, b));
        const long R = R0 + r;
        const int bidx = (int)(R >> 10);
        const int t = (int)(R & 1023);
        g_z0[((long)t * BB + bidx) * HH + h] = u.x + u.y;
    }
}

// ============================================================================
// Kernel 2: producer/consumer scan (R13 structure & mapping verbatim; CH=8,
// NRING=8 for lower pipeline lag; MUFU tanh).
//   warp 2r   (A): layer-0 recurrence, writes h0/t0 chunks into shared ring
//   warp 2r+1 (B): layer-1 recurrence, reads ring, writes ts1 (transition)
// ============================================================================
__global__ __launch_bounds__(256) void k_scan2(
    const float* __restrict__ eWhh0, const float* __restrict__ eWih1,
    const float* __restrict__ eWhh1, const float* __restrict__ ebih1,
    const float* __restrict__ ebhh1,
    const float* __restrict__ tWhh0, const float* __restrict__ tbih0,
    const float* __restrict__ tbhh0, const float* __restrict__ tWih1,
    const float* __restrict__ tWhh1, const float* __restrict__ tbih1,
    const float* __restrict__ tbhh1) {
    __shared__ __align__(16) float ring[4][NRING][CH][HH];  // 32 KB
    __shared__ __align__(16) float sA[4][2][HH];
    __shared__ __align__(16) float sB[4][2][HH];
    __shared__ volatile int prod[4];
    __shared__ volatile int cons[4];

    const int tid = threadIdx.x;
    const int lane = tid & 31;
    const int w = tid >> 5;
    const int r = w >> 1;         // local row 0..3  (R13 mapping)
    const int role = w & 1;       // 0 = producer, 1 = consumer
    const int b = blockIdx.x * 4 + r;
    const int ST = BB * HH;

    if (tid < 4) { prod[tid] = 0; cons[tid] = 0; }
    __syncthreads();

    if (role == 0) {
        // ================= producer: layer-0 chains =================
        u64 wp[16];
        LOAD_WROW(wp, eWhh0)
        sA[r][0][lane] = 0.0f;
        WBAR();

        const float* zp = g_z0 + (long)b * HH + lane;
        float zbuf[8];
#pragma unroll
        for (int i = 0; i < 8; i++) zbuf[i] = zp[(long)i * ST];

        float h = 0.0f;
        for (int k = 0; k < ENC_CHUNKS; k++) {
            if (k >= NRING) {
                while (cons[r] < k - (NRING - 1)) __nanosleep(32);
            }
            WBAR();
            float* slot = (float*)&ring[r][k & (NRING - 1)][0][0];
#pragma unroll
            for (int s = 0; s < CH; s++) {
                const int t = k * CH + s;
                const int cur = t & 1, nxt = cur ^ 1;
                const float zin = zbuf[t & 7];
                if (t + 8 < TT) zbuf[t & 7] = zp[(long)(t + 8) * ST];
                h = ftanh(dot32w(wp, sA[r][cur], zin));
                sA[r][nxt][lane] = h;
                slot[s * HH + lane] = h;
                WBAR();
            }
            __threadfence_block();
            __syncwarp();
            if (lane == 0) prod[r] = k + 1;
        }
        const float hT0 = h;

        // transition layer 0: t0[p] = tanh(bias0 + Whh0 . t0[p-1])
        LOAD_WROW(wp, tWhh0)
        const float bias0 = tbih0[lane] + tbhh0[lane];
        sA[r][0][lane] = hT0;
        WBAR();

        for (int k = 0; k < TRA_CHUNKS; k++) {
            const int gk = ENC_CHUNKS + k;
            while (cons[r] < gk - (NRING - 1)) __nanosleep(32);
            WBAR();
            float* slot = (float*)&ring[r][gk & (NRING - 1)][0][0];
#pragma unroll
            for (int s = 0; s < CH; s++) {
                const int p = k * CH + s;
                const int cur = p & 1, nxt = cur ^ 1;
                h = ftanh(dot32w(wp, sA[r][cur], bias0));
                sA[r][nxt][lane] = h;
                slot[s * HH + lane] = h;
                WBAR();
            }
            __threadfence_block();
            __syncwarp();
            if (lane == 0) prod[r] = gk + 1;
        }
    } else {
        // ================= consumer: layer-1 chains =================
        u64 wip[16], whp[16];
        LOAD_WROW(wip, eWih1)
        LOAD_WROW(whp, eWhh1)
        float bias1 = ebih1[lane] + ebhh1[lane];
        sB[r][0][lane] = 0.0f;
        WBAR();

        float h1 = 0.0f;
        for (int k = 0; k < ENC_CHUNKS; k++) {
            while (prod[r] < k + 1) __nanosleep(32);
            __threadfence_block();
            WBAR();
            const float* slot = (const float*)&ring[r][k & (NRING - 1)][0][0];
#pragma unroll
            for (int s = 0; s < CH; s++) {
                const int t = k * CH + s;
                const int cur = t & 1, nxt = cur ^ 1;
                const float d1 = dot32w(wip, &slot[s * HH], bias1);
                const float d2 = dot32w(whp, sB[r][cur], 0.0f);
                h1 = ftanh(d1 + d2);
                sB[r][nxt][lane] = h1;
                WBAR();
            }
            __threadfence_block();
            __syncwarp();
            if (lane == 0) cons[r] = k + 1;
        }
        const float hT1 = h1;

        // transition layer 1: t1[p] = tanh(bias1 + Wih1 . t0[p] + Whh1 . t1[p-1])
        LOAD_WROW(wip, tWih1)
        LOAD_WROW(whp, tWhh1)
        bias1 = tbih1[lane] + tbhh1[lane];
        sB[r][0][lane] = hT1;
        WBAR();

        float* tp = g_ts1 + (long)b * HH + lane;
        for (int k = 0; k < TRA_CHUNKS; k++) {
            const int gk = ENC_CHUNKS + k;
            while (prod[r] < gk + 1) __nanosleep(32);
            __threadfence_block();
            WBAR();
            const float* slot = (const float*)&ring[r][gk & (NRING - 1)][0][0];
#pragma unroll
            for (int s = 0; s < CH; s++) {
                const int p = k * CH + s;
                const int cur = p & 1, nxt = cur ^ 1;
                const float d1 = dot32w(wip, &slot[s * HH], bias1);
                const float d2 = dot32w(whp, sB[r][cur], 0.0f);
                h1 = ftanh(d1 + d2);
                tp[(long)p * ST] = h1;
                sB[r][nxt][lane] = h1;
                WBAR();
            }
            __threadfence_block();
            __syncwarp();
            if (lane == 0) cons[r] = gk + 1;
        }
    }
}

// ============================================================================
// Kernel 3: observation MLP (verified: 137us). 128-row tile,
// launch_bounds(256,2), fast gelu.
// ============================================================================
#define MLP_SMEM_FLOATS (4096 + 2304 + 4352 + 8192 + 128)

__global__ __launch_bounds__(256, 2) void k_mlp(const float* __restrict__ W1,
                                                const float* __restrict__ b1,
                                                const float* __restrict__ W2,
                                                const float* __restrict__ b2,
                                                float* __restrict__ out) {
    extern __shared__ __align__(16) float sm[];
    float* Xs  = sm;                  // [128][32]
    float* W1s = sm + 4096;           // [64][36]
    float* W2s = sm + 6400;           // [64][68]
    float* Gs  = sm + 10752;          // [128][64]
    float* b1s = sm + 18944;
    float* b2s = sm + 19008;

    const int tid = threadIdx.x;
    const int tx = tid & 15;          // col: e_j = tx + 16*j
    const int ty = tid >> 4;          // rows 8*ty .. 8*ty+7
    const int p0 = blockIdx.x * 16;
    const int b0 = blockIdx.y * 8;

    for (int i4 = tid; i4 < 1024; i4 += 256) {
        const int r = i4 >> 3, c4 = i4 & 7;
        const int bl = r >> 4, pl = r & 15;
        ((float4*)Xs)[i4] =
            *(const float4*)&g_ts1[((long)(p0 + pl) * BB + (b0 + bl)) * HH + 4 * c4];
    }
    for (int i4 = tid; i4 < 512; i4 += 256) {
        const int j = i4 >> 3, k4 = i4 & 7;
        ((float4*)W1s)[j * 9 + k4] = ((const float4*)W1)[i4];
    }
    for (int i4 = tid; i4 < 1024; i4 += 256) {
        const int e = i4 >> 4, j4 = i4 & 15;
        ((float4*)W2s)[e * 17 + j4] = ((const float4*)W2)[i4];
    }
    if (tid < 64) b1s[tid] = b1[tid];
    else if (tid < 128) b2s[tid - 64] = b2[tid - 64];
    __syncthreads();

    u64 acc[8][4];
#pragma unroll
    for (int i = 0; i < 8; i++)
#pragma unroll
        for (int j = 0; j < 4; j++) acc[i][j] = pk(b1s[tx + 16 * j], 0.0f);

#pragma unroll
    for (int k4 = 0; k4 < 8; k4++) {
        ulonglong2 wv[4];
#pragma unroll
        for (int j = 0; j < 4; j++)
            wv[j] = *(const ulonglong2*)&W1s[(tx + 16 * j) * 36 + 4 * k4];
#pragma unroll
        for (int i = 0; i < 8; i++) {
            ulonglong2 xv = *(const ulonglong2*)&Xs[(8 * ty + i) * 32 + 4 * k4];
#pragma unroll
            for (int j = 0; j < 4; j++) {
                acc[i][j] = fma2(xv.x, wv[j].x, acc[i][j]);
                acc[i][j] = fma2(xv.y, wv[j].y, acc[i][j]);
            }
        }
    }

#pragma unroll
    for (int i = 0; i < 8; i++) {
#pragma unroll
        for (int j = 0; j < 4; j++) {
            float2 uj = upk(acc[i][j]);
            Gs[(8 * ty + i) * 64 + tx + 16 * j] = gelu(uj.x + uj.y);
        }
    }
    __syncthreads();

#pragma unroll
    for (int i = 0; i < 8; i++)
#pragma unroll
        for (int j = 0; j < 4; j++) acc[i][j] = pk(b2s[tx + 16 * j], 0.0f);

#pragma unroll
    for (int k4 = 0; k4 < 16; k4++) {
        ulonglong2 wv[4];
#pragma unroll
        for (int j = 0; j < 4; j++)
            wv[j] = *(const ulonglong2*)&W2s[(tx + 16 * j) * 68 + 4 * k4];
#pragma unroll
        for (int i = 0; i < 8; i++) {
            ulonglong2 gv = *(const ulonglong2*)&Gs[(8 * ty + i) * 64 + 4 * k4];
#pragma unroll
            for (int j = 0; j < 4; j++) {
                acc[i][j] = fma2(gv.x, wv[j].x, acc[i][j]);
                acc[i][j] = fma2(gv.y, wv[j].y, acc[i][j]);
            }
        }
    }

    float y[8][4];
#pragma unroll
    for (int i = 0; i < 8; i++)
#pragma unroll
        for (int j = 0; j < 4; j++) {
            float2 uj = upk(acc[i][j]);
            y[i][j] = uj.x + uj.y;
        }

    const int bl = ty >> 1;
    const int plb = (ty & 1) * 8;
    float* ob = out + (long)(b0 + bl) * EE * PP + p0 + plb;
#pragma unroll
    for (int j = 0; j < 4; j++) {
        const int e = tx + 16 * j;
#pragma unroll
        for (int q = 0; q < 2; q++) {
            float4 v;
            v.x = y[4 * q + 0][j]; v.y = y[4 * q + 1][j];
            v.z = y[4 * q + 2][j]; v.w = y[4 * q + 3][j];
            *(float4*)&ob[(long)e * PP + 4 * q] = v;
        }
    }
}

// ============================================================================
extern "C" void kernel_launch(void* const* d_in, const int* in_sizes, int n_in,
                              void* d_out, int out_size) {
    (void)in_sizes; (void)n_in; (void)out_size;
    const float* x      = (const float*)d_in[0];
    const float* e_Wih0 = (const float*)d_in[1];
    const float* e_Whh0 = (const float*)d_in[2];
    const float* e_bih0 = (const float*)d_in[3];
    const float* e_bhh0 = (const float*)d_in[4];
    const float* e_Wih1 = (const float*)d_in[5];
    const float* e_Whh1 = (const float*)d_in[6];
    const float* e_bih1 = (const float*)d_in[7];
    const float* e_bhh1 = (const float*)d_in[8];
    // d_in[9] = t_Wih0: unused (transition input is zeros)
    const float* t_Whh0 = (const float*)d_in[10];
    const float* t_bih0 = (const float*)d_in[11];
    const float* t_bhh0 = (const float*)d_in[12];
    const float* t_Wih1 = (const float*)d_in[13];
    const float* t_Whh1 = (const float*)d_in[14];
    const float* t_bih1 = (const float*)d_in[15];
    const float* t_bhh1 = (const float*)d_in[16];
    const float* o_W1   = (const float*)d_in[17];
    const float* o_b1   = (const float*)d_in[18];
    const float* o_W2   = (const float*)d_in[19];
    const float* o_b2   = (const float*)d_in[20];
    float* out = (float*)d_out;

    cudaFuncSetAttribute(k_mlp, cudaFuncAttributeMaxDynamicSharedMemorySize,
                         MLP_SMEM_FLOATS * 4);

    k_z0<<<(BB * TT) / 64, 256>>>(x, e_Wih0, e_bih0, e_bhh0);
    k_scan2<<<BB / 4, 256>>>(e_Whh0, e_Wih1, e_Whh1, e_bih1, e_bhh1,
                             t_Whh0, t_bih0, t_bhh0, t_Wih1, t_Whh1,
                             t_bih1, t_bhh1);
    dim3 g(PP / 16, BB / 8);
    k_mlp<<<g, 256, MLP_SMEM_FLOATS * 4>>>(o_W1, o_b1, o_W2, o_b2, out);
}

// round 17
// speedup vs baseline: 1.2666x; 1.0051x over previous
#include <cuda_runtime.h>
#include <math.h>

#define BB 512
#define TT 1024
#define EE 64
#define HH 32
#define PP 720

#define CH 8                        // steps per ring chunk
#define NRING 8                     // ring depth (chunks)
#define ENC_CHUNKS (TT / CH)        // 128
#define TRA_CHUNKS (PP / CH)        // 90

typedef unsigned long long u64;

// ---------------- scratch (device globals: no allocation allowed) ----------
__device__ float g_z0[(size_t)TT * BB * HH];   // [t][b][h]
__device__ float g_ts1[(size_t)PP * BB * HH];  // [p][b][h]

#define WBAR() asm volatile("" ::: "memory")

// ---------------- packed fp32x2 helpers (Blackwell FFMA2) ------------------
__device__ __forceinline__ u64 pk(float a, float b) {
    u64 r; asm("mov.b64 %0, {%1,%2};" : "=l"(r) : "f"(a), "f"(b)); return r;
}
__device__ __forceinline__ float2 upk(u64 v) {
    float2 r; asm("mov.b64 {%0,%1}, %2;" : "=f"(r.x), "=f"(r.y) : "l"(v)); return r;
}
__device__ __forceinline__ u64 fma2(u64 a, u64 b, u64 c) {
    u64 d; asm("fma.rn.f32x2 %0, %1, %2, %3;" : "=l"(d) : "l"(a), "l"(b), "l"(c)); return d;
}
__device__ __forceinline__ u64 add2(u64 a, u64 b) {
    u64 d; asm("add.rn.f32x2 %0, %1, %2;" : "=l"(d) : "l"(a), "l"(b)); return d;
}

// hardware tanh (MUFU.TANH): single 16-cyc MUFU, abs err ~5e-4.
// R16-verified: final rel_err 2.7e-6, 400x inside budget.
__device__ __forceinline__ float ftanh(float x) {
    float r; asm("tanh.approx.f32 %0, %1;" : "=f"(r) : "f"(x)); return r;
}

// exact-GELU via Abramowitz-Stegun 7.1.26 erf (abs err <= 1.5e-7).
__device__ __forceinline__ float gelu(float x) {
    const float u = x * 0.70710678118654752f;
    const float au = fabsf(u);
    const float t = __fdividef(1.0f, fmaf(0.3275911f, au, 1.0f));
    const float e = __expf(-u * u);
    float p = fmaf(t, 1.061405429f, -1.453152027f);
    p = fmaf(t, p, 1.421413741f);
    p = fmaf(t, p, -0.284496736f);
    p = fmaf(t, p, 0.254829592f);
    const float erf_abs = fmaf(-p * t, e, 1.0f);
    const float er = copysignf(erf_abs, u);
    return 0.5f * x * (1.0f + er);
}

// dot(32-float shared vector, packed weight row) + init; 4 split chains
__device__ __forceinline__ float dot32w(const u64* wp,
                                        const float* __restrict__ sh,
                                        float init) {
    const u64 ZZ = pk(0.0f, 0.0f);
    u64 a = pk(init, 0.0f), b = ZZ, c = ZZ, d = ZZ;
#pragma unroll
    for (int q = 0; q < 4; q++) {
        ulonglong2 v0 = *(const ulonglong2*)&sh[8 * q];
        ulonglong2 v1 = *(const ulonglong2*)&sh[8 * q + 4];
        a = fma2(v0.x, wp[4 * q + 0], a);
        b = fma2(v0.y, wp[4 * q + 1], b);
        c = fma2(v1.x, wp[4 * q + 2], c);
        d = fma2(v1.y, wp[4 * q + 3], d);
    }
    float2 r = upk(add2(add2(a, b), add2(c, d)));
    return r.x + r.y;
}

#define LOAD_WROW(DST, SRC)                                                    \
    _Pragma("unroll")                                                          \
    for (int i = 0; i < 8; i++) {                                              \
        float4 v = *(const float4*)&(SRC)[lane * HH + 4 * i];                  \
        (DST)[2 * i] = pk(v.x, v.y);                                           \
        (DST)[2 * i + 1] = pk(v.z, v.w);                                       \
    }

// ============================================================================
// Kernel 1: z0. 128-row tiles (grid 4096) to halve per-block DRAM-latency
// startup occurrences; 4-chain accumulators (FFMA2 depth 8).
// ============================================================================
__global__ __launch_bounds__(256) void k_z0(const float* __restrict__ x,
                                            const float* __restrict__ Wih0,
                                            const float* __restrict__ bih0,
                                            const float* __restrict__ bhh0) {
    __shared__ __align__(16) float Xs[128 * EE];   // 32 KB
    __shared__ float WsT[EE * 33];
    __shared__ float bs[HH];

    const int tid = threadIdx.x;
    const long R0 = (long)blockIdx.x * 128;

    {
        const float4* src = (const float4*)(x + R0 * EE);
        float4* dst = (float4*)Xs;
#pragma unroll
        for (int i = 0; i < 8; i++) dst[tid + 256 * i] = src[tid + 256 * i];
    }
    for (int i4 = tid; i4 < 512; i4 += 256) {
        float4 v = ((const float4*)Wih0)[i4];
        const int h = i4 >> 4;
        const int e0 = (i4 & 15) * 4;
        WsT[(e0 + 0) * 33 + h] = v.x;
        WsT[(e0 + 1) * 33 + h] = v.y;
        WsT[(e0 + 2) * 33 + h] = v.z;
        WsT[(e0 + 3) * 33 + h] = v.w;
    }
    if (tid < HH) bs[tid] = bih0[tid] + bhh0[tid];
    __syncthreads();

    const int h = tid & 31;
    const int rbase = tid >> 5;

    u64 wp[EE / 2];
#pragma unroll
    for (int k = 0; k < EE / 2; k++)
        wp[k] = pk(WsT[(2 * k) * 33 + h], WsT[(2 * k + 1) * 33 + h]);
    const float bias = bs[h];

#pragma unroll
    for (int rr = 0; rr < 16; rr++) {
        const int r = rbase + 8 * rr;
        u64 a = pk(bias, 0.0f), b = pk(0.0f, 0.0f);
        u64 c = pk(0.0f, 0.0f), d = pk(0.0f, 0.0f);
#pragma unroll
        for (int e8 = 0; e8 < EE / 8; e8++) {
            ulonglong2 x0 = *(const ulonglong2*)&Xs[r * EE + 8 * e8];      // bcast
            ulonglong2 x1 = *(const ulonglong2*)&Xs[r * EE + 8 * e8 + 4];  // bcast
            a = fma2(x0.x, wp[4 * e8 + 0], a);
            b = fma2(x0.y, wp[4 * e8 + 1], b);
            c = fma2(x1.x, wp[4 * e8 + 2], c);
            d = fma2(x1.y, wp[4 * e8 + 3], d);
        }
        float2 u = upk(add2(add2(a, b), add2(c, d)));
        const long R = R0 + r;
        const int bidx = (int)(R >> 10);
        const int t = (int)(R & 1023);
        g_z0[((long)t * BB + bidx) * HH + h] = u.x + u.y;
    }
}

// ============================================================================
// Kernel 2: producer/consumer scan (R16-verified: CH=8, NRING=8, MUFU tanh).
//   warp 2r   (A): layer-0 recurrence, writes h0/t0 chunks into shared ring
//   warp 2r+1 (B): layer-1 recurrence, reads ring, writes ts1 (transition)
// ============================================================================
__global__ __launch_bounds__(256) void k_scan2(
    const float* __restrict__ eWhh0, const float* __restrict__ eWih1,
    const float* __restrict__ eWhh1, const float* __restrict__ ebih1,
    const float* __restrict__ ebhh1,
    const float* __restrict__ tWhh0, const float* __restrict__ tbih0,
    const float* __restrict__ tbhh0, const float* __restrict__ tWih1,
    const float* __restrict__ tWhh1, const float* __restrict__ tbih1,
    const float* __restrict__ tbhh1) {
    __shared__ __align__(16) float ring[4][NRING][CH][HH];  // 32 KB
    __shared__ __align__(16) float sA[4][2][HH];
    __shared__ __align__(16) float sB[4][2][HH];
    __shared__ volatile int prod[4];
    __shared__ volatile int cons[4];

    const int tid = threadIdx.x;
    const int lane = tid & 31;
    const int w = tid >> 5;
    const int r = w >> 1;         // local row 0..3
    const int role = w & 1;       // 0 = producer, 1 = consumer
    const int b = blockIdx.x * 4 + r;
    const int ST = BB * HH;

    if (tid < 4) { prod[tid] = 0; cons[tid] = 0; }
    __syncthreads();

    if (role == 0) {
        // ================= producer: layer-0 chains =================
        u64 wp[16];
        LOAD_WROW(wp, eWhh0)
        sA[r][0][lane] = 0.0f;
        WBAR();

        const float* zp = g_z0 + (long)b * HH + lane;
        float zbuf[8];
#pragma unroll
        for (int i = 0; i < 8; i++) zbuf[i] = zp[(long)i * ST];

        float h = 0.0f;
        for (int k = 0; k < ENC_CHUNKS; k++) {
            if (k >= NRING) {
                while (cons[r] < k - (NRING - 1)) __nanosleep(32);
            }
            WBAR();
            float* slot = (float*)&ring[r][k & (NRING - 1)][0][0];
#pragma unroll
            for (int s = 0; s < CH; s++) {
                const int t = k * CH + s;
                const int cur = t & 1, nxt = cur ^ 1;
                const float zin = zbuf[t & 7];
                if (t + 8 < TT) zbuf[t & 7] = zp[(long)(t + 8) * ST];
                h = ftanh(dot32w(wp, sA[r][cur], zin));
                sA[r][nxt][lane] = h;
                slot[s * HH + lane] = h;
                WBAR();
            }
            __threadfence_block();
            __syncwarp();
            if (lane == 0) prod[r] = k + 1;
        }
        const float hT0 = h;

        // transition layer 0: t0[p] = tanh(bias0 + Whh0 . t0[p-1])
        LOAD_WROW(wp, tWhh0)
        const float bias0 = tbih0[lane] + tbhh0[lane];
        sA[r][0][lane] = hT0;
        WBAR();

        for (int k = 0; k < TRA_CHUNKS; k++) {
            const int gk = ENC_CHUNKS + k;
            while (cons[r] < gk - (NRING - 1)) __nanosleep(32);
            WBAR();
            float* slot = (float*)&ring[r][gk & (NRING - 1)][0][0];
#pragma unroll
            for (int s = 0; s < CH; s++) {
                const int p = k * CH + s;
                const int cur = p & 1, nxt = cur ^ 1;
                h = ftanh(dot32w(wp, sA[r][cur], bias0));
                sA[r][nxt][lane] = h;
                slot[s * HH + lane] = h;
                WBAR();
            }
            __threadfence_block();
            __syncwarp();
            if (lane == 0) prod[r] = gk + 1;
        }
    } else {
        // ================= consumer: layer-1 chains =================
        u64 wip[16], whp[16];
        LOAD_WROW(wip, eWih1)
        LOAD_WROW(whp, eWhh1)
        float bias1 = ebih1[lane] + ebhh1[lane];
        sB[r][0][lane] = 0.0f;
        WBAR();

        float h1 = 0.0f;
        for (int k = 0; k < ENC_CHUNKS; k++) {
            while (prod[r] < k + 1) __nanosleep(32);
            __threadfence_block();
            WBAR();
            const float* slot = (const float*)&ring[r][k & (NRING - 1)][0][0];
#pragma unroll
            for (int s = 0; s < CH; s++) {
                const int t = k * CH + s;
                const int cur = t & 1, nxt = cur ^ 1;
                const float d1 = dot32w(wip, &slot[s * HH], bias1);
                const float d2 = dot32w(whp, sB[r][cur], 0.0f);
                h1 = ftanh(d1 + d2);
                sB[r][nxt][lane] = h1;
                WBAR();
            }
            __threadfence_block();
            __syncwarp();
            if (lane == 0) cons[r] = k + 1;
        }
        const float hT1 = h1;

        // transition layer 1: t1[p] = tanh(bias1 + Wih1 . t0[p] + Whh1 . t1[p-1])
        LOAD_WROW(wip, tWih1)
        LOAD_WROW(whp, tWhh1)
        bias1 = tbih1[lane] + tbhh1[lane];
        sB[r][0][lane] = hT1;
        WBAR();

        float* tp = g_ts1 + (long)b * HH + lane;
        for (int k = 0; k < TRA_CHUNKS; k++) {
            const int gk = ENC_CHUNKS + k;
            while (prod[r] < gk + 1) __nanosleep(32);
            __threadfence_block();
            WBAR();
            const float* slot = (const float*)&ring[r][gk & (NRING - 1)][0][0];
#pragma unroll
            for (int s = 0; s < CH; s++) {
                const int p = k * CH + s;
                const int cur = p & 1, nxt = cur ^ 1;
                const float d1 = dot32w(wip, &slot[s * HH], bias1);
                const float d2 = dot32w(whp, sB[r][cur], 0.0f);
                h1 = ftanh(d1 + d2);
                tp[(long)p * ST] = h1;
                sB[r][nxt][lane] = h1;
                WBAR();
            }
            __threadfence_block();
            __syncwarp();
            if (lane == 0) cons[r] = gk + 1;
        }
    }
}

// ============================================================================
// Kernel 3: observation MLP (verified: 137us). 128-row tile,
// launch_bounds(256,2), fast gelu.
// ============================================================================
#define MLP_SMEM_FLOATS (4096 + 2304 + 4352 + 8192 + 128)

__global__ __launch_bounds__(256, 2) void k_mlp(const float* __restrict__ W1,
                                                const float* __restrict__ b1,
                                                const float* __restrict__ W2,
                                                const float* __restrict__ b2,
                                                float* __restrict__ out) {
    extern __shared__ __align__(16) float sm[];
    float* Xs  = sm;                  // [128][32]
    float* W1s = sm + 4096;           // [64][36]
    float* W2s = sm + 6400;           // [64][68]
    float* Gs  = sm + 10752;          // [128][64]
    float* b1s = sm + 18944;
    float* b2s = sm + 19008;

    const int tid = threadIdx.x;
    const int tx = tid & 15;          // col: e_j = tx + 16*j
    const int ty = tid >> 4;          // rows 8*ty .. 8*ty+7
    const int p0 = blockIdx.x * 16;
    const int b0 = blockIdx.y * 8;

    for (int i4 = tid; i4 < 1024; i4 += 256) {
        const int r = i4 >> 3, c4 = i4 & 7;
        const int bl = r >> 4, pl = r & 15;
        ((float4*)Xs)[i4] =
            *(const float4*)&g_ts1[((long)(p0 + pl) * BB + (b0 + bl)) * HH + 4 * c4];
    }
    for (int i4 = tid; i4 < 512; i4 += 256) {
        const int j = i4 >> 3, k4 = i4 & 7;
        ((float4*)W1s)[j * 9 + k4] = ((const float4*)W1)[i4];
    }
    for (int i4 = tid; i4 < 1024; i4 += 256) {
        const int e = i4 >> 4, j4 = i4 & 15;
        ((float4*)W2s)[e * 17 + j4] = ((const float4*)W2)[i4];
    }
    if (tid < 64) b1s[tid] = b1[tid];
    else if (tid < 128) b2s[tid - 64] = b2[tid - 64];
    __syncthreads();

    u64 acc[8][4];
#pragma unroll
    for (int i = 0; i < 8; i++)
#pragma unroll
        for (int j = 0; j < 4; j++) acc[i][j] = pk(b1s[tx + 16 * j], 0.0f);

#pragma unroll
    for (int k4 = 0; k4 < 8; k4++) {
        ulonglong2 wv[4];
#pragma unroll
        for (int j = 0; j < 4; j++)
            wv[j] = *(const ulonglong2*)&W1s[(tx + 16 * j) * 36 + 4 * k4];
#pragma unroll
        for (int i = 0; i < 8; i++) {
            ulonglong2 xv = *(const ulonglong2*)&Xs[(8 * ty + i) * 32 + 4 * k4];
#pragma unroll
            for (int j = 0; j < 4; j++) {
                acc[i][j] = fma2(xv.x, wv[j].x, acc[i][j]);
                acc[i][j] = fma2(xv.y, wv[j].y, acc[i][j]);
            }
        }
    }

#pragma unroll
    for (int i = 0; i < 8; i++) {
#pragma unroll
        for (int j = 0; j < 4; j++) {
            float2 uj = upk(acc[i][j]);
            Gs[(8 * ty + i) * 64 + tx + 16 * j] = gelu(uj.x + uj.y);
        }
    }
    __syncthreads();

#pragma unroll
    for (int i = 0; i < 8; i++)
#pragma unroll
        for (int j = 0; j < 4; j++) acc[i][j] = pk(b2s[tx + 16 * j], 0.0f);

#pragma unroll
    for (int k4 = 0; k4 < 16; k4++) {
        ulonglong2 wv[4];
#pragma unroll
        for (int j = 0; j < 4; j++)
            wv[j] = *(const ulonglong2*)&W2s[(tx + 16 * j) * 68 + 4 * k4];
#pragma unroll
        for (int i = 0; i < 8; i++) {
            ulonglong2 gv = *(const ulonglong2*)&Gs[(8 * ty + i) * 64 + 4 * k4];
#pragma unroll
            for (int j = 0; j < 4; j++) {
                acc[i][j] = fma2(gv.x, wv[j].x, acc[i][j]);
                acc[i][j] = fma2(gv.y, wv[j].y, acc[i][j]);
            }
        }
    }

    float y[8][4];
#pragma unroll
    for (int i = 0; i < 8; i++)
#pragma unroll
        for (int j = 0; j < 4; j++) {
            float2 uj = upk(acc[i][j]);
            y[i][j] = uj.x + uj.y;
        }

    const int bl = ty >> 1;
    const int plb = (ty & 1) * 8;
    float* ob = out + (long)(b0 + bl) * EE * PP + p0 + plb;
#pragma unroll
    for (int j = 0; j < 4; j++) {
        const int e = tx + 16 * j;
#pragma unroll
        for (int q = 0; q < 2; q++) {
            float4 v;
            v.x = y[4 * q + 0][j]; v.y = y[4 * q + 1][j];
            v.z = y[4 * q + 2][j]; v.w = y[4 * q + 3][j];
            *(float4*)&ob[(long)e * PP + 4 * q] = v;
        }
    }
}

// ============================================================================
extern "C" void kernel_launch(void* const* d_in, const int* in_sizes, int n_in,
                              void* d_out, int out_size) {
    (void)in_sizes; (void)n_in; (void)out_size;
    const float* x      = (const float*)d_in[0];
    const float* e_Wih0 = (const float*)d_in[1];
    const float* e_Whh0 = (const float*)d_in[2];
    const float* e_bih0 = (const float*)d_in[3];
    const float* e_bhh0 = (const float*)d_in[4];
    const float* e_Wih1 = (const float*)d_in[5];
    const float* e_Whh1 = (const float*)d_in[6];
    const float* e_bih1 = (const float*)d_in[7];
    const float* e_bhh1 = (const float*)d_in[8];
    // d_in[9] = t_Wih0: unused (transition input is zeros)
    const float* t_Whh0 = (const float*)d_in[10];
    const float* t_bih0 = (const float*)d_in[11];
    const float* t_bhh0 = (const float*)d_in[12];
    const float* t_Wih1 = (const float*)d_in[13];
    const float* t_Whh1 = (const float*)d_in[14];
    const float* t_bih1 = (const float*)d_in[15];
    const float* t_bhh1 = (const float*)d_in[16];
    const float* o_W1   = (const float*)d_in[17];
    const float* o_b1   = (const float*)d_in[18];
    const float* o_W2   = (const float*)d_in[19];
    const float* o_b2   = (const float*)d_in[20];
    float* out = (float*)d_out;

    cudaFuncSetAttribute(k_mlp, cudaFuncAttributeMaxDynamicSharedMemorySize,
                         MLP_SMEM_FLOATS * 4);

    k_z0<<<(BB * TT) / 128, 256>>>(x, e_Wih0, e_bih0, e_bhh0);
    k_scan2<<<BB / 4, 256>>>(e_Whh0, e_Wih1, e_Whh1, e_bih1, e_bhh1,
                             t_Whh0, t_bih0, t_bhh0, t_Wih1, t_Whh1,
                             t_bih1, t_bhh1);
    dim3 g(PP / 16, BB / 8);
    k_mlp<<<g, 256, MLP_SMEM_FLOATS * 4>>>(o_W1, o_b1, o_W2, o_b2, out);
}